// round 6
// baseline (speedup 1.0000x reference)
#include <cuda_runtime.h>
#include <cuda_fp16.h>
#include <cstdint>
#include <cstddef>

static constexpr int BB = 8, SSQ = 4096, DIN = 256, HH = 512;
static constexpr int M = BB * SSQ;        // 32768
static constexpr int KE = 512;            // [xh | xl] K-concat
static constexpr int NG = 4 * HH;         // 2048
static constexpr float EPSF = 1e-6f;
static constexpr int LCH = 128, NCH = SSQ / LCH, NCHAIN = BB * HH;

static constexpr int PAD = 40;            // smem row stride (halfs); LDSM conflict-free
static constexpr int BM = 128, BN = 128, BK = 32;
static constexpr int NKT = KE / BK;       // 16
static constexpr int A_BYTES = BM * PAD * 2;   // 10240
static constexpr int B_BYTES = BN * PAD * 2;   // 10240
static constexpr int STGB = A_BYTES + B_BYTES; // 20480
static constexpr int NSTAGE = 4;
static constexpr int SMEM_DYN = NSTAGE * STGB; // 81920
static constexpr int SST = 132;                // staging row stride (floats)
static constexpr int SEG_OFF = 128 * SST;      // floats; seg summaries after staging

static __device__ __half g_Ah[(size_t)M * KE];     // 32 MB
static __device__ __half g_Bh[(size_t)NG * KE];    // 2 MB
static __device__ float  g_G[(size_t)M * NG];      // 256 MB: float4(o,P,c_loc,n_loc) per (m,h)
static __device__ float  g_Pa[NCHAIN * NCH];
static __device__ float  g_Ci[NCHAIN * NCH];
static __device__ float  g_Ni[NCHAIN * NCH];

__device__ __forceinline__ uint32_t smem_u32(const void* p) {
    uint32_t a;
    asm("{ .reg .u64 t; cvta.to.shared.u64 t, %1; cvt.u32.u64 %0, t; }" : "=r"(a) : "l"(p));
    return a;
}

// ---------------- prep A: [xh | xl], row-major K-contig ----------------
__global__ void xl_prepA(const float* __restrict__ x) {
    int gid = blockIdx.x * blockDim.x + threadIdx.x;       // M*64 threads
    int j = gid & 63, m = gid >> 6;
    int k = j * 4;
    float4 v = *reinterpret_cast<const float4*>(x + (size_t)m * DIN + k);
    __half h[4], l[4];
    float vv[4] = {v.x, v.y, v.z, v.w};
#pragma unroll
    for (int t = 0; t < 4; t++) {
        h[t] = __float2half_rn(vv[t]);
        l[t] = __float2half_rn(vv[t] - __half2float(h[t]));
    }
    __half* row = g_Ah + (size_t)m * KE;
    *reinterpret_cast<uint2*>(row + k)       = *reinterpret_cast<uint2*>(h);
    *reinterpret_cast<uint2*>(row + 256 + k) = *reinterpret_cast<uint2*>(l);
}

// ------- prep B: row n' = h*4 + gate; cols [Wh ; Wh] (2-term split) -------
__global__ void xl_prepB(const float* __restrict__ Wi, const float* __restrict__ Wf,
                         const float* __restrict__ Wo, const float* __restrict__ Wz) {
    int gid = blockIdx.x * blockDim.x + threadIdx.x;       // NG*128 threads
    int j = gid & 127, n = gid >> 7;
    int keff = j * 4;
    int ks = keff & 255;
    int g = n & 3, h = n >> 2;
    const float* W = (g == 0) ? Wi : (g == 1) ? Wf : (g == 2) ? Wo : Wz;
    __half out[4];
#pragma unroll
    for (int t = 0; t < 4; t++)
        out[t] = __float2half_rn(W[(size_t)(ks + t) * HH + h]);
    *reinterpret_cast<uint2*>(g_Bh + (size_t)n * KE + keff) = *reinterpret_cast<uint2*>(out);
}

// ------- GEMM (ldmatrix, 4-stage cp.async, single-sync) + fused chunk scan ---
#define LDSM_X4(r, addr) \
    asm volatile("ldmatrix.sync.aligned.m8n8.x4.shared.b16 {%0,%1,%2,%3}, [%4];" \
        : "=r"((r)[0]), "=r"((r)[1]), "=r"((r)[2]), "=r"((r)[3]) : "r"(addr))

__global__ __launch_bounds__(256, 2) void xl_gemm(const float* __restrict__ bi, const float* __restrict__ bfg,
                                                  const float* __restrict__ bo, const float* __restrict__ bz) {
    extern __shared__ char smem[];
    const uint32_t sbase = smem_u32(smem);
    const int tid = threadIdx.x, lane = tid & 31, wid = tid >> 5;
    const int bm = blockIdx.y * BM, bn = blockIdx.x * BN;
    const int warp_m = (wid & 1) * 64, warp_n = (wid >> 1) * 32;
    const int grp = lane >> 2, tq = lane & 3;

    float acc[4][4][4];
#pragma unroll
    for (int a = 0; a < 4; a++)
#pragma unroll
        for (int b = 0; b < 4; b++)
#pragma unroll
            for (int c = 0; c < 4; c++) acc[a][b][c] = 0.f;

    const int rsel = (lane & 7) + ((lane >> 3) & 1) * 8;
    const int csel = (lane >> 4) * 8;
    const uint32_t a_base = sbase + (uint32_t)((warp_m + rsel) * PAD + csel) * 2;
    const uint32_t b_base = sbase + A_BYTES + (uint32_t)((warp_n + rsel) * PAD + csel) * 2;

    auto issue = [&](int kt, int st) {
        uint32_t sa = sbase + st * STGB;
#pragma unroll
        for (int i = 0; i < 2; i++) {
            int idx = tid + i * 256;
            int r = idx >> 2, c = idx & 3;
            const __half* ga = g_Ah + (size_t)(bm + r) * KE + kt * BK + c * 8;
            asm volatile("cp.async.cg.shared.global [%0], [%1], 16;"
                :: "r"(sa + (uint32_t)(r * PAD + c * 8) * 2), "l"(ga));
        }
        uint32_t sb = sbase + st * STGB + A_BYTES;
#pragma unroll
        for (int i = 0; i < 2; i++) {
            int idx = tid + i * 256;
            int r = idx >> 2, c = idx & 3;
            const __half* gb = g_Bh + (size_t)(bn + r) * KE + kt * BK + c * 8;
            asm volatile("cp.async.cg.shared.global [%0], [%1], 16;"
                :: "r"(sb + (uint32_t)(r * PAD + c * 8) * 2), "l"(gb));
        }
        asm volatile("cp.async.commit_group;" ::: "memory");
    };

    issue(0, 0); issue(1, 1); issue(2, 2);
    for (int kt = 0; kt < NKT; kt++) {
        int st = kt & 3;
        if (kt < NKT - 2) {
            asm volatile("cp.async.wait_group 2;" ::: "memory");
        } else {
            asm volatile("cp.async.wait_group 0;" ::: "memory");
        }
        __syncthreads();
        if (kt + 3 < NKT) issue(kt + 3, (kt + 3) & 3);
        uint32_t ab = a_base + st * STGB;
        uint32_t bb = b_base + st * STGB;
#pragma unroll
        for (int ks = 0; ks < BK; ks += 16) {
            uint32_t afr[4][4], bfr[2][4];
#pragma unroll
            for (int im = 0; im < 4; im++)
                LDSM_X4(afr[im], ab + (uint32_t)(im * 16 * PAD + ks) * 2);
#pragma unroll
            for (int ip = 0; ip < 2; ip++)
                LDSM_X4(bfr[ip], bb + (uint32_t)(ip * 16 * PAD + ks) * 2);
#pragma unroll
            for (int im = 0; im < 4; im++)
#pragma unroll
                for (int ip = 0; ip < 2; ip++) {
                    asm volatile(
                        "mma.sync.aligned.m16n8k16.row.col.f32.f16.f16.f32 "
                        "{%0,%1,%2,%3}, {%4,%5,%6,%7}, {%8,%9}, {%0,%1,%2,%3};"
                        : "+f"(acc[im][2 * ip][0]), "+f"(acc[im][2 * ip][1]),
                          "+f"(acc[im][2 * ip][2]), "+f"(acc[im][2 * ip][3])
                        : "r"(afr[im][0]), "r"(afr[im][1]), "r"(afr[im][2]), "r"(afr[im][3]),
                          "r"(bfr[ip][0]), "r"(bfr[ip][2]));
                    asm volatile(
                        "mma.sync.aligned.m16n8k16.row.col.f32.f16.f16.f32 "
                        "{%0,%1,%2,%3}, {%4,%5,%6,%7}, {%8,%9}, {%0,%1,%2,%3};"
                        : "+f"(acc[im][2 * ip + 1][0]), "+f"(acc[im][2 * ip + 1][1]),
                          "+f"(acc[im][2 * ip + 1][2]), "+f"(acc[im][2 * ip + 1][3])
                        : "r"(afr[im][0]), "r"(afr[im][1]), "r"(afr[im][2]), "r"(afr[im][3]),
                          "r"(bfr[ip][1]), "r"(bfr[ip][3]));
                }
        }
    }
    __syncthreads();   // mainloop smem dead; reuse for staging

    // ---- stage activated gates into smem [128 rows][SST] ----
    float* sg = reinterpret_cast<float*>(smem);
#pragma unroll
    for (int im = 0; im < 4; im++)
#pragma unroll
        for (int in = 0; in < 4; in++) {
            int col0 = bn + warp_n + in * 8 + tq * 2;      // n' global, even
            int g0 = col0 & 3;                              // 0 (i,f) or 2 (o,z)
            int h = col0 >> 2;
            float b0, b1;
            if (g0 == 0) { b0 = bi[h]; b1 = bfg[h]; } else { b0 = bo[h]; b1 = bz[h]; }
#pragma unroll
            for (int hrow = 0; hrow < 2; hrow++) {
                int row = warp_m + im * 16 + grp + hrow * 8;
                float a0 = acc[im][in][hrow * 2 + 0] + b0;
                float a1 = acc[im][in][hrow * 2 + 1] + b1;
                float o0, o1;
                if (g0 == 0) {  // i = exp(clip), f = exp(clip)
                    o0 = __expf(fminf(fmaxf(a0, -20.f), 0.f));
                    o1 = __expf(fminf(fmaxf(a1, -20.f), 0.f));
                } else {        // o = sigmoid, z = tanh
                    o0 = 1.f / (1.f + __expf(-a0));
                    float t1 = __expf(2.f * fminf(fmaxf(a1, -15.f), 15.f));
                    o1 = __fdividef(t1 - 1.f, t1 + 1.f);
                }
                int colL = col0 - bn;
                sg[row * SST + colL] = o0;
                sg[row * SST + colL + 1] = o1;
            }
        }
    __syncthreads();

    // ---- fused chunk scan: 32 chains x 8 segments x 16 steps ----
    const int chain = tid >> 3, seg = tid & 7;
    float* segS = sg + SEG_OFF;   // [32][8][3]
    {
        float P = 1.f, C = 0.f, N = 0.f;
        const float* col = sg + chain * 4;
#pragma unroll 4
        for (int u = 0; u < 16; u++) {
            int s = seg * 16 + u;
            float iv = col[s * SST + 0], fv = col[s * SST + 1], zv = col[s * SST + 3];
            C = fv * C + iv * zv;
            N = fv * N + iv;
            P *= fv;
        }
        segS[(chain * 8 + seg) * 3 + 0] = P;
        segS[(chain * 8 + seg) * 3 + 1] = C;
        segS[(chain * 8 + seg) * 3 + 2] = N;
    }
    __syncthreads();
    {
        float Pp = 1.f, cI = 0.f, nI = 0.f;
        for (int t = 0; t < seg; t++) {
            float P = segS[(chain * 8 + t) * 3 + 0];
            float C = segS[(chain * 8 + t) * 3 + 1];
            float N = segS[(chain * 8 + t) * 3 + 2];
            cI = P * cI + C;
            nI = P * nI + N;
            Pp *= P;
        }
        const int mt = blockIdx.y;
        const int b = mt >> 5, ch = mt & 31;
        const size_t m0 = (size_t)b * SSQ + (size_t)ch * LCH;
        const int hg = (bn >> 2) + chain;
        float4* gS = reinterpret_cast<float4*>(g_G);
        const float* col = sg + chain * 4;
        float c = cI, n = nI, P = Pp;
#pragma unroll 4
        for (int u = 0; u < 16; u++) {
            int s = seg * 16 + u;
            float iv = col[s * SST + 0], fv = col[s * SST + 1];
            float ov = col[s * SST + 2], zv = col[s * SST + 3];
            c = fv * c + iv * zv;
            n = fv * n + iv;
            P *= fv;
            gS[(m0 + s) * HH + hg] = make_float4(ov, P, c, n);
        }
        if (seg == 7) {
            int idx = (b * NCH + ch) * HH + hg;
            g_Pa[idx] = P; g_Ci[idx] = c; g_Ni[idx] = n;
        }
    }
}

// ---------------- chunk-level scan: overwrite with chunk inits ----------------
__global__ void xl_scan2() {
    int t = blockIdx.x * blockDim.x + threadIdx.x;   // 4096
    int h = t & 511, b = t >> 9;
    float c = 0.f, n = 1.f;
    for (int ch = 0; ch < NCH; ch++) {
        int idx = (b * NCH + ch) * HH + h;
        float P = g_Pa[idx], Cl = g_Ci[idx], Nl = g_Ni[idx];
        g_Ci[idx] = c; g_Ni[idx] = n;
        c = P * c + Cl;
        n = P * n + Nl;
    }
}

// ---------------- final: h = o*(c_loc + P*cI)/(n_loc + P*nI + eps) ----------
__global__ void xl_final(float* __restrict__ out) {
    int t = blockIdx.x * blockDim.x + threadIdx.x;   // 131072
    int h = t & 511, ch = (t >> 9) & 31, b = t >> 14;
    int idx = (b * NCH + ch) * HH + h;
    float cI = g_Ci[idx], nI = g_Ni[idx];
    const float4* base = reinterpret_cast<const float4*>(g_G)
        + ((size_t)(b * SSQ + ch * LCH)) * HH + h;
    float* ob = out + ((size_t)(b * SSQ + ch * LCH)) * HH + h;
    for (int s = 0; s < LCH; s++) {
        float4 v = base[(size_t)s * HH];
        ob[(size_t)s * HH] = v.x * (v.z + v.y * cI) / (v.w + v.y * nI + EPSF);
    }
}

extern "C" void kernel_launch(void* const* d_in, const int* in_sizes, int n_in,
                              void* d_out, int out_size) {
    const float* x  = (const float*)d_in[0];
    const float* Wi = (const float*)d_in[1];
    const float* bi = (const float*)d_in[2];
    const float* Wf = (const float*)d_in[3];
    const float* bf = (const float*)d_in[4];
    const float* Wo = (const float*)d_in[5];
    const float* bo = (const float*)d_in[6];
    const float* Wz = (const float*)d_in[7];
    const float* bz = (const float*)d_in[8];
    float* out = (float*)d_out;

    cudaFuncSetAttribute(xl_gemm, cudaFuncAttributeMaxDynamicSharedMemorySize, SMEM_DYN);

    xl_prepA<<<(M * 64) / 256, 256>>>(x);
    xl_prepB<<<(NG * 128) / 256, 256>>>(Wi, Wf, Wo, Wz);
    xl_gemm<<<dim3(NG / BN, M / BM), 256, SMEM_DYN>>>(bi, bf, bo, bz);
    xl_scan2<<<NCHAIN / 256, 256>>>();
    xl_final<<<(NCHAIN * NCH) / 256, 256>>>(out);
}

// round 7
// speedup vs baseline: 1.8317x; 1.8317x over previous
#include <cuda_runtime.h>
#include <cuda_fp16.h>
#include <cstdint>
#include <cstddef>

static constexpr int BB = 8, SSQ = 4096, DIN = 256, HH = 512;
static constexpr int M = BB * SSQ;        // 32768
static constexpr int KE = 256;            // single fp16 term
static constexpr int NG = 4 * HH;         // 2048
static constexpr float EPSF = 1e-6f;
static constexpr int LCH = 128, NCH = SSQ / LCH, NCHAIN = BB * HH;

static constexpr int PAD = 40;            // smem row stride (halfs); LDSM conflict-free
static constexpr int BM = 128, BN = 128, BK = 32;
static constexpr int NKT = KE / BK;       // 8
static constexpr int A_BYTES = BM * PAD * 2;   // 10240
static constexpr int B_BYTES = BN * PAD * 2;   // 10240
static constexpr int STGB = A_BYTES + B_BYTES; // 20480
static constexpr int NSTAGE = 4;
static constexpr int SMEM_DYN = NSTAGE * STGB; // 81920

static __device__ __half g_Ah[(size_t)M * KE];     // 16 MB
static __device__ __half g_Bh[(size_t)NG * KE];    // 1 MB
static __device__ float  g_G[(size_t)M * NG];      // 256 MB gates (i,f,o,z)
static __device__ float  g_Pa[NCHAIN * NCH];
static __device__ float  g_Ci[NCHAIN * NCH];
static __device__ float  g_Ni[NCHAIN * NCH];

__device__ __forceinline__ uint32_t smem_u32(const void* p) {
    uint32_t a;
    asm("{ .reg .u64 t; cvta.to.shared.u64 t, %1; cvt.u32.u64 %0, t; }" : "=r"(a) : "l"(p));
    return a;
}

// ---------------- prep A: fp16(x), row-major K-contig ----------------
__global__ void xl_prepA(const float* __restrict__ x) {
    int gid = blockIdx.x * blockDim.x + threadIdx.x;       // M*64 threads, 4 k each
    int j = gid & 63, m = gid >> 6;
    int k = j * 4;
    float4 v = *reinterpret_cast<const float4*>(x + (size_t)m * DIN + k);
    __half h[4] = {__float2half_rn(v.x), __float2half_rn(v.y),
                   __float2half_rn(v.z), __float2half_rn(v.w)};
    *reinterpret_cast<uint2*>(g_Ah + (size_t)m * KE + k) = *reinterpret_cast<uint2*>(h);
}

// ---------------- prep B: rows n (gate*512+h), fp16(W) ----------
__global__ void xl_prepB(const float* __restrict__ Wi, const float* __restrict__ Wf,
                         const float* __restrict__ Wo, const float* __restrict__ Wz) {
    int gid = blockIdx.x * blockDim.x + threadIdx.x;       // NG*64 threads, 4 k each
    int j = gid & 63, n = gid >> 6;
    int k = j * 4;
    int g = n >> 9, nc = n & 511;
    const float* W = (g == 0) ? Wi : (g == 1) ? Wf : (g == 2) ? Wo : Wz;
    __half out[4];
#pragma unroll
    for (int t = 0; t < 4; t++)
        out[t] = __float2half_rn(W[(size_t)(k + t) * HH + nc]);
    *reinterpret_cast<uint2*>(g_Bh + (size_t)n * KE + k) = *reinterpret_cast<uint2*>(out);
}

// ---------------- GEMM (ldmatrix + 4-stage cp.async) + activation epilogue ---
#define LDSM_X4(r, addr) \
    asm volatile("ldmatrix.sync.aligned.m8n8.x4.shared.b16 {%0,%1,%2,%3}, [%4];" \
        : "=r"((r)[0]), "=r"((r)[1]), "=r"((r)[2]), "=r"((r)[3]) : "r"(addr))

__global__ __launch_bounds__(256, 2) void xl_gemm(const float* __restrict__ bi, const float* __restrict__ bfg,
                                                  const float* __restrict__ bo, const float* __restrict__ bz) {
    extern __shared__ char smem[];
    const uint32_t sbase = smem_u32(smem);
    const int tid = threadIdx.x, lane = tid & 31, wid = tid >> 5;
    const int bm = blockIdx.y * BM, bn = blockIdx.x * BN;
    const int warp_m = (wid & 1) * 64, warp_n = (wid >> 1) * 32;
    const int grp = lane >> 2, tq = lane & 3;

    float acc[4][4][4];
#pragma unroll
    for (int a = 0; a < 4; a++)
#pragma unroll
        for (int b = 0; b < 4; b++)
#pragma unroll
            for (int c = 0; c < 4; c++) acc[a][b][c] = 0.f;

    const int rsel = (lane & 7) + ((lane >> 3) & 1) * 8;
    const int csel = (lane >> 4) * 8;
    const uint32_t a_base = sbase + (uint32_t)((warp_m + rsel) * PAD + csel) * 2;
    const uint32_t b_base = sbase + A_BYTES + (uint32_t)((warp_n + rsel) * PAD + csel) * 2;

    auto issue = [&](int kt, int st) {
        uint32_t sa = sbase + st * STGB;
#pragma unroll
        for (int i = 0; i < 2; i++) {                      // A: 512 int4
            int idx = tid + i * 256;
            int r = idx >> 2, c = idx & 3;
            const __half* ga = g_Ah + (size_t)(bm + r) * KE + kt * BK + c * 8;
            asm volatile("cp.async.cg.shared.global [%0], [%1], 16;"
                :: "r"(sa + (uint32_t)(r * PAD + c * 8) * 2), "l"(ga));
        }
        uint32_t sb = sbase + st * STGB + A_BYTES;
#pragma unroll
        for (int i = 0; i < 2; i++) {                      // B: 512 int4
            int idx = tid + i * 256;
            int r = idx >> 2, c = idx & 3;
            const __half* gb = g_Bh + (size_t)(bn + r) * KE + kt * BK + c * 8;
            asm volatile("cp.async.cg.shared.global [%0], [%1], 16;"
                :: "r"(sb + (uint32_t)(r * PAD + c * 8) * 2), "l"(gb));
        }
        asm volatile("cp.async.commit_group;" ::: "memory");
    };

    issue(0, 0); issue(1, 1); issue(2, 2);
    for (int kt = 0; kt < NKT; kt++) {
        int st = kt & 3;
        if (kt + 3 < NKT) {
            issue(kt + 3, (kt + 3) & 3);
            asm volatile("cp.async.wait_group 3;" ::: "memory");
        } else {
            asm volatile("cp.async.wait_group 0;" ::: "memory");
        }
        __syncthreads();
        uint32_t ab = a_base + st * STGB;
        uint32_t bb = b_base + st * STGB;
#pragma unroll
        for (int ks = 0; ks < BK; ks += 16) {
            uint32_t afr[4][4], bfr[2][4];
#pragma unroll
            for (int im = 0; im < 4; im++)
                LDSM_X4(afr[im], ab + (uint32_t)(im * 16 * PAD + ks) * 2);
#pragma unroll
            for (int ip = 0; ip < 2; ip++)
                LDSM_X4(bfr[ip], bb + (uint32_t)(ip * 16 * PAD + ks) * 2);
#pragma unroll
            for (int im = 0; im < 4; im++)
#pragma unroll
                for (int ip = 0; ip < 2; ip++) {
                    asm volatile(
                        "mma.sync.aligned.m16n8k16.row.col.f32.f16.f16.f32 "
                        "{%0,%1,%2,%3}, {%4,%5,%6,%7}, {%8,%9}, {%0,%1,%2,%3};"
                        : "+f"(acc[im][2 * ip][0]), "+f"(acc[im][2 * ip][1]),
                          "+f"(acc[im][2 * ip][2]), "+f"(acc[im][2 * ip][3])
                        : "r"(afr[im][0]), "r"(afr[im][1]), "r"(afr[im][2]), "r"(afr[im][3]),
                          "r"(bfr[ip][0]), "r"(bfr[ip][2]));
                    asm volatile(
                        "mma.sync.aligned.m16n8k16.row.col.f32.f16.f16.f32 "
                        "{%0,%1,%2,%3}, {%4,%5,%6,%7}, {%8,%9}, {%0,%1,%2,%3};"
                        : "+f"(acc[im][2 * ip + 1][0]), "+f"(acc[im][2 * ip + 1][1]),
                          "+f"(acc[im][2 * ip + 1][2]), "+f"(acc[im][2 * ip + 1][3])
                        : "r"(afr[im][0]), "r"(afr[im][1]), "r"(afr[im][2]), "r"(afr[im][3]),
                          "r"(bfr[ip][1]), "r"(bfr[ip][3]));
                }
        }
        __syncthreads();
    }

    // epilogue: gate constant per block (4 blocks of 128 per gate)
    const int g = blockIdx.x >> 2;
    const float* bias = (g == 0) ? bi : (g == 1) ? bfg : (g == 2) ? bo : bz;
#pragma unroll
    for (int im = 0; im < 4; im++)
#pragma unroll
        for (int in = 0; in < 4; in++) {
            int row0 = bm + warp_m + im * 16 + grp;
            int col0 = bn + warp_n + in * 8 + tq * 2;
            float b0 = bias[col0 & (HH - 1)], b1 = bias[(col0 + 1) & (HH - 1)];
#pragma unroll
            for (int hrow = 0; hrow < 2; hrow++) {
                int row = row0 + hrow * 8;
                float a0 = acc[im][in][hrow * 2 + 0] + b0;
                float a1 = acc[im][in][hrow * 2 + 1] + b1;
                float2 o;
                if (g < 2) {
                    o.x = __expf(fminf(fmaxf(a0, -20.f), 0.f));
                    o.y = __expf(fminf(fmaxf(a1, -20.f), 0.f));
                } else if (g == 2) {
                    o.x = 1.f / (1.f + __expf(-a0));
                    o.y = 1.f / (1.f + __expf(-a1));
                } else {
                    float t0 = __expf(2.f * fminf(fmaxf(a0, -15.f), 15.f));
                    float t1 = __expf(2.f * fminf(fmaxf(a1, -15.f), 15.f));
                    o.x = __fdividef(t0 - 1.f, t0 + 1.f);
                    o.y = __fdividef(t1 - 1.f, t1 + 1.f);
                }
                *reinterpret_cast<float2*>(g_G + (size_t)row * NG + col0) = o;
            }
        }
}

// ---------------- scan pass 1: per-chunk local (P, C, N) ----------------
__global__ void xl_scan1() {
    int t = blockIdx.x * blockDim.x + threadIdx.x;   // 131072
    int h = t & 511, ch = (t >> 9) & 31, b = t >> 14;
    float P = 1.f, C = 0.f, N = 0.f;
    const float* base = g_G + ((size_t)(b * SSQ + ch * LCH)) * NG + h;
    for (int s = 0; s < LCH; s++) {
        const float* p = base + (size_t)s * NG;
        float iv = p[0], fv = p[512], zv = p[1536];
        C = fv * C + iv * zv;
        N = fv * N + iv;
        P *= fv;
    }
    int idx = (b * NCH + ch) * HH + h;
    g_Pa[idx] = P; g_Ci[idx] = C; g_Ni[idx] = N;
}

// ---------------- scan pass 2: chunk-level scan, overwrite with inits -------
__global__ void xl_scan2() {
    int t = blockIdx.x * blockDim.x + threadIdx.x;   // 4096
    int h = t & 511, b = t >> 9;
    float c = 0.f, n = 1.f;
    for (int ch = 0; ch < NCH; ch++) {
        int idx = (b * NCH + ch) * HH + h;
        float P = g_Pa[idx], Cl = g_Ci[idx], Nl = g_Ni[idx];
        g_Ci[idx] = c; g_Ni[idx] = n;
        c = P * c + Cl;
        n = P * n + Nl;
    }
}

// ---------------- scan pass 3: recompute with inits, emit h ----------------
__global__ void xl_scan3(float* __restrict__ out) {
    int t = blockIdx.x * blockDim.x + threadIdx.x;   // 131072
    int h = t & 511, ch = (t >> 9) & 31, b = t >> 14;
    int idx = (b * NCH + ch) * HH + h;
    float c = g_Ci[idx], n = g_Ni[idx];
    const float* base = g_G + ((size_t)(b * SSQ + ch * LCH)) * NG + h;
    float* ob = out + ((size_t)(b * SSQ + ch * LCH)) * HH + h;
    for (int s = 0; s < LCH; s++) {
        const float* p = base + (size_t)s * NG;
        float iv = p[0], fv = p[512], ov = p[1024], zv = p[1536];
        c = fv * c + iv * zv;
        n = fv * n + iv;
        ob[(size_t)s * HH] = ov * (c / (n + EPSF));
    }
}

extern "C" void kernel_launch(void* const* d_in, const int* in_sizes, int n_in,
                              void* d_out, int out_size) {
    const float* x  = (const float*)d_in[0];
    const float* Wi = (const float*)d_in[1];
    const float* bi = (const float*)d_in[2];
    const float* Wf = (const float*)d_in[3];
    const float* bf = (const float*)d_in[4];
    const float* Wo = (const float*)d_in[5];
    const float* bo = (const float*)d_in[6];
    const float* Wz = (const float*)d_in[7];
    const float* bz = (const float*)d_in[8];
    float* out = (float*)d_out;

    cudaFuncSetAttribute(xl_gemm, cudaFuncAttributeMaxDynamicSharedMemorySize, SMEM_DYN);

    xl_prepA<<<(M * 64) / 256, 256>>>(x);
    xl_prepB<<<(NG * 64) / 256, 256>>>(Wi, Wf, Wo, Wz);
    xl_gemm<<<dim3(NG / BN, M / BM), 256, SMEM_DYN>>>(bi, bf, bo, bz);
    xl_scan1<<<(NCHAIN * NCH) / 256, 256>>>();
    xl_scan2<<<NCHAIN / 256, 256>>>();
    xl_scan3<<<(NCHAIN * NCH) / 256, 256>>>(out);
}

// round 8
// speedup vs baseline: 2.0233x; 1.1046x over previous
#include <cuda_runtime.h>
#include <cuda_fp16.h>
#include <cstdint>
#include <cstddef>

static constexpr int BB = 8, SSQ = 4096, DIN = 256, HH = 512;
static constexpr int M = BB * SSQ;        // 32768
static constexpr int KE = 256;            // single fp16 term
static constexpr int NG = 4 * HH;         // 2048
static constexpr float EPSF = 1e-6f;
static constexpr int LCH = 128, NCH = SSQ / LCH;   // 32 chunks

static constexpr int PAD = 40;            // smem row stride (halfs); LDSM conflict-free
static constexpr int BM = 128, BN = 128, BK = 32;
static constexpr int NKT = KE / BK;       // 8
static constexpr int A_BYTES = BM * PAD * 2;   // 10240
static constexpr int B_BYTES = BN * PAD * 2;   // 10240
static constexpr int STGB = A_BYTES + B_BYTES; // 20480
static constexpr int NSTAGE = 4;
static constexpr int SMEM_DYN = NSTAGE * STGB; // 81920

static __device__ __half g_Ah[(size_t)M * KE];     // 16 MB
static __device__ __half g_Bh[(size_t)NG * KE];    // 1 MB
static __device__ __half g_Gh[(size_t)M * NG];     // 128 MB gates (i,f,o,z) fp16

__device__ __forceinline__ uint32_t smem_u32(const void* p) {
    uint32_t a;
    asm("{ .reg .u64 t; cvta.to.shared.u64 t, %1; cvt.u32.u64 %0, t; }" : "=r"(a) : "l"(p));
    return a;
}

// ---------------- prep A: fp16(x), row-major K-contig ----------------
__global__ void xl_prepA(const float* __restrict__ x) {
    int gid = blockIdx.x * blockDim.x + threadIdx.x;       // M*64 threads, 4 k each
    int j = gid & 63, m = gid >> 6;
    int k = j * 4;
    float4 v = *reinterpret_cast<const float4*>(x + (size_t)m * DIN + k);
    __half h[4] = {__float2half_rn(v.x), __float2half_rn(v.y),
                   __float2half_rn(v.z), __float2half_rn(v.w)};
    *reinterpret_cast<uint2*>(g_Ah + (size_t)m * KE + k) = *reinterpret_cast<uint2*>(h);
}

// ---------------- prep B: rows n (gate*512+h), fp16(W) ----------
__global__ void xl_prepB(const float* __restrict__ Wi, const float* __restrict__ Wf,
                         const float* __restrict__ Wo, const float* __restrict__ Wz) {
    int gid = blockIdx.x * blockDim.x + threadIdx.x;       // NG*64 threads, 4 k each
    int j = gid & 63, n = gid >> 6;
    int k = j * 4;
    int g = n >> 9, nc = n & 511;
    const float* W = (g == 0) ? Wi : (g == 1) ? Wf : (g == 2) ? Wo : Wz;
    __half out[4];
#pragma unroll
    for (int t = 0; t < 4; t++)
        out[t] = __float2half_rn(W[(size_t)(k + t) * HH + nc]);
    *reinterpret_cast<uint2*>(g_Bh + (size_t)n * KE + k) = *reinterpret_cast<uint2*>(out);
}

// ---------------- GEMM (ldmatrix + 4-stage cp.async) + activation epilogue ---
#define LDSM_X4(r, addr) \
    asm volatile("ldmatrix.sync.aligned.m8n8.x4.shared.b16 {%0,%1,%2,%3}, [%4];" \
        : "=r"((r)[0]), "=r"((r)[1]), "=r"((r)[2]), "=r"((r)[3]) : "r"(addr))

__global__ __launch_bounds__(256, 2) void xl_gemm(const float* __restrict__ bi, const float* __restrict__ bfg,
                                                  const float* __restrict__ bo, const float* __restrict__ bz) {
    extern __shared__ char smem[];
    const uint32_t sbase = smem_u32(smem);
    const int tid = threadIdx.x, lane = tid & 31, wid = tid >> 5;
    const int bm = blockIdx.y * BM, bn = blockIdx.x * BN;
    const int warp_m = (wid & 1) * 64, warp_n = (wid >> 1) * 32;
    const int grp = lane >> 2, tq = lane & 3;

    float acc[4][4][4];
#pragma unroll
    for (int a = 0; a < 4; a++)
#pragma unroll
        for (int b = 0; b < 4; b++)
#pragma unroll
            for (int c = 0; c < 4; c++) acc[a][b][c] = 0.f;

    const int rsel = (lane & 7) + ((lane >> 3) & 1) * 8;
    const int csel = (lane >> 4) * 8;
    const uint32_t a_base = sbase + (uint32_t)((warp_m + rsel) * PAD + csel) * 2;
    const uint32_t b_base = sbase + A_BYTES + (uint32_t)((warp_n + rsel) * PAD + csel) * 2;

    auto issue = [&](int kt, int st) {
        uint32_t sa = sbase + st * STGB;
#pragma unroll
        for (int i = 0; i < 2; i++) {                      // A: 512 int4
            int idx = tid + i * 256;
            int r = idx >> 2, c = idx & 3;
            const __half* ga = g_Ah + (size_t)(bm + r) * KE + kt * BK + c * 8;
            asm volatile("cp.async.cg.shared.global [%0], [%1], 16;"
                :: "r"(sa + (uint32_t)(r * PAD + c * 8) * 2), "l"(ga));
        }
        uint32_t sb = sbase + st * STGB + A_BYTES;
#pragma unroll
        for (int i = 0; i < 2; i++) {                      // B: 512 int4
            int idx = tid + i * 256;
            int r = idx >> 2, c = idx & 3;
            const __half* gb = g_Bh + (size_t)(bn + r) * KE + kt * BK + c * 8;
            asm volatile("cp.async.cg.shared.global [%0], [%1], 16;"
                :: "r"(sb + (uint32_t)(r * PAD + c * 8) * 2), "l"(gb));
        }
        asm volatile("cp.async.commit_group;" ::: "memory");
    };

    issue(0, 0); issue(1, 1); issue(2, 2);
    for (int kt = 0; kt < NKT; kt++) {
        int st = kt & 3;
        if (kt + 3 < NKT) {
            issue(kt + 3, (kt + 3) & 3);
            asm volatile("cp.async.wait_group 3;" ::: "memory");
        } else {
            asm volatile("cp.async.wait_group 0;" ::: "memory");
        }
        __syncthreads();
        uint32_t ab = a_base + st * STGB;
        uint32_t bb = b_base + st * STGB;
#pragma unroll
        for (int ks = 0; ks < BK; ks += 16) {
            uint32_t afr[4][4], bfr[2][4];
#pragma unroll
            for (int im = 0; im < 4; im++)
                LDSM_X4(afr[im], ab + (uint32_t)(im * 16 * PAD + ks) * 2);
#pragma unroll
            for (int ip = 0; ip < 2; ip++)
                LDSM_X4(bfr[ip], bb + (uint32_t)(ip * 16 * PAD + ks) * 2);
#pragma unroll
            for (int im = 0; im < 4; im++)
#pragma unroll
                for (int ip = 0; ip < 2; ip++) {
                    asm volatile(
                        "mma.sync.aligned.m16n8k16.row.col.f32.f16.f16.f32 "
                        "{%0,%1,%2,%3}, {%4,%5,%6,%7}, {%8,%9}, {%0,%1,%2,%3};"
                        : "+f"(acc[im][2 * ip][0]), "+f"(acc[im][2 * ip][1]),
                          "+f"(acc[im][2 * ip][2]), "+f"(acc[im][2 * ip][3])
                        : "r"(afr[im][0]), "r"(afr[im][1]), "r"(afr[im][2]), "r"(afr[im][3]),
                          "r"(bfr[ip][0]), "r"(bfr[ip][2]));
                    asm volatile(
                        "mma.sync.aligned.m16n8k16.row.col.f32.f16.f16.f32 "
                        "{%0,%1,%2,%3}, {%4,%5,%6,%7}, {%8,%9}, {%0,%1,%2,%3};"
                        : "+f"(acc[im][2 * ip + 1][0]), "+f"(acc[im][2 * ip + 1][1]),
                          "+f"(acc[im][2 * ip + 1][2]), "+f"(acc[im][2 * ip + 1][3])
                        : "r"(afr[im][0]), "r"(afr[im][1]), "r"(afr[im][2]), "r"(afr[im][3]),
                          "r"(bfr[ip][1]), "r"(bfr[ip][3]));
                }
        }
        __syncthreads();
    }

    // epilogue: gate constant per block (4 blocks of 128 per gate); fp16 stores
    const int g = blockIdx.x >> 2;
    const float* bias = (g == 0) ? bi : (g == 1) ? bfg : (g == 2) ? bo : bz;
#pragma unroll
    for (int im = 0; im < 4; im++)
#pragma unroll
        for (int in = 0; in < 4; in++) {
            int row0 = bm + warp_m + im * 16 + grp;
            int col0 = bn + warp_n + in * 8 + tq * 2;
            float b0 = bias[col0 & (HH - 1)], b1 = bias[(col0 + 1) & (HH - 1)];
#pragma unroll
            for (int hrow = 0; hrow < 2; hrow++) {
                int row = row0 + hrow * 8;
                float a0 = acc[im][in][hrow * 2 + 0] + b0;
                float a1 = acc[im][in][hrow * 2 + 1] + b1;
                float o0, o1;
                if (g < 2) {
                    o0 = __expf(fminf(fmaxf(a0, -20.f), 0.f));
                    o1 = __expf(fminf(fmaxf(a1, -20.f), 0.f));
                } else if (g == 2) {
                    o0 = 1.f / (1.f + __expf(-a0));
                    o1 = 1.f / (1.f + __expf(-a1));
                } else {
                    float t0 = __expf(2.f * fminf(fmaxf(a0, -15.f), 15.f));
                    float t1 = __expf(2.f * fminf(fmaxf(a1, -15.f), 15.f));
                    o0 = __fdividef(t0 - 1.f, t0 + 1.f);
                    o1 = __fdividef(t1 - 1.f, t1 + 1.f);
                }
                *reinterpret_cast<__half2*>(g_Gh + (size_t)row * NG + col0)
                    = __floats2half2_rn(o0, o1);
            }
        }
}

// ------- fused scan: block = 32 h x 32 chunks; smem affine scan over chunks --
__global__ __launch_bounds__(1024, 1) void xl_scan(float* __restrict__ out) {
    __shared__ float sP[NCH][33], sC[NCH][33], sN[NCH][33];
    const int hl = threadIdx.x & 31, ch = threadIdx.x >> 5;
    const int h = blockIdx.x * 32 + hl;
    const int b = blockIdx.y;
    const size_t row0 = (size_t)b * SSQ + (size_t)ch * LCH;
    const __half* base = g_Gh + row0 * NG + h;

    // pass 1: chunk-local (P, C, N)
    float P = 1.f, C = 0.f, N = 0.f;
    for (int s = 0; s < LCH; s++) {
        const __half* p = base + (size_t)s * NG;
        float iv = __half2float(p[0]), fv = __half2float(p[512]), zv = __half2float(p[1536]);
        C = fv * C + iv * zv;
        N = fv * N + iv;
        P *= fv;
    }
    sP[ch][hl] = P; sC[ch][hl] = C; sN[ch][hl] = N;
    __syncthreads();

    // Hillis-Steele inclusive affine scan over ch (cur ∘ prev)
#pragma unroll
    for (int d = 1; d < NCH; d <<= 1) {
        float p2 = 0.f, c2 = 0.f, n2 = 0.f;
        bool act = (ch >= d);
        if (act) { p2 = sP[ch - d][hl]; c2 = sC[ch - d][hl]; n2 = sN[ch - d][hl]; }
        __syncthreads();
        if (act) {
            C = P * c2 + C;
            N = P * n2 + N;
            P = P * p2;
            sP[ch][hl] = P; sC[ch][hl] = C; sN[ch][hl] = N;
        }
        __syncthreads();
    }

    // exclusive init for this chunk applied to (c0,n0) = (0,1)
    float c = 0.f, n = 1.f;
    if (ch > 0) {
        c = sC[ch - 1][hl];
        n = sN[ch - 1][hl] + sP[ch - 1][hl];
    }

    // pass 3: recompute with init, emit h
    float* ob = out + row0 * HH + h;
    for (int s = 0; s < LCH; s++) {
        const __half* p = base + (size_t)s * NG;
        float iv = __half2float(p[0]), fv = __half2float(p[512]);
        float ov = __half2float(p[1024]), zv = __half2float(p[1536]);
        c = fv * c + iv * zv;
        n = fv * n + iv;
        ob[(size_t)s * HH] = ov * (c / (n + EPSF));
    }
}

extern "C" void kernel_launch(void* const* d_in, const int* in_sizes, int n_in,
                              void* d_out, int out_size) {
    const float* x  = (const float*)d_in[0];
    const float* Wi = (const float*)d_in[1];
    const float* bi = (const float*)d_in[2];
    const float* Wf = (const float*)d_in[3];
    const float* bf = (const float*)d_in[4];
    const float* Wo = (const float*)d_in[5];
    const float* bo = (const float*)d_in[6];
    const float* Wz = (const float*)d_in[7];
    const float* bz = (const float*)d_in[8];
    float* out = (float*)d_out;

    cudaFuncSetAttribute(xl_gemm, cudaFuncAttributeMaxDynamicSharedMemorySize, SMEM_DYN);

    xl_prepA<<<(M * 64) / 256, 256>>>(x);
    xl_prepB<<<(NG * 64) / 256, 256>>>(Wi, Wf, Wo, Wz);
    xl_gemm<<<dim3(NG / BN, M / BM), 256, SMEM_DYN>>>(bi, bf, bo, bz);
    xl_scan<<<dim3(HH / 32, BB), 1024>>>(out);
}